// round 2
// baseline (speedup 1.0000x reference)
#include <cuda_runtime.h>
#include <cstdint>
#include <cstddef>

// Problem constants
constexpr int cB   = 256;
constexpr int cT   = 128;
constexpr int cOBS = 512;
constexpr int cE   = 1024;
constexpr int cH   = 1024;
constexpr int cA   = 64;
constexpr int cBT  = cB * cT;        // 32768
constexpr int cG   = 4 * cH;         // 4096

// Output layout (flat tuple order): logits, values, obs_pred, rew_pred, hT, cT
constexpr size_t OFF_LOGITS = 0;
constexpr size_t OFF_VAL    = OFF_LOGITS + (size_t)cBT * cA;        // 2,097,152
constexpr size_t OFF_OBS    = OFF_VAL + (size_t)cBT;                // 2,129,920
constexpr size_t OFF_REW    = OFF_OBS + (size_t)cBT * cOBS;         // 18,907,136
constexpr size_t OFF_HT     = OFF_REW + (size_t)cBT;                // 18,939,904
constexpr size_t OFF_CT     = OFF_HT + (size_t)cB * cH;             // 19,202,048

// Scratch (device globals; no runtime allocation allowed)
__device__ float g_enc1[(size_t)cBT * cE];   // encoder hidden 1, reused as LN output x
__device__ float g_enc2[(size_t)cBT * cE];   // encoder output
__device__ float g_gx[(size_t)cBT * cG];     // [T, B, 4H]
__device__ float g_hseq[(size_t)cBT * cH];   // [B, T, H]
__device__ float g_gates[(size_t)cB * cG];   // per-step gates
__device__ float g_hbuf[2][(size_t)cB * cH];
__device__ float g_cbuf[2][(size_t)cB * cH];

// ---------------------------------------------------------------------------
// Generic SGEMM: C[M,N] = A[M,K] (row-major) * B, with epilogues.
// TRANSB=false: B is [K,N] row-major. TRANSB=true: B is [N,K] row-major.
// EPI: 0 = +bias ; 1 = silu(+bias) ; 2 = +bias+bias2, row swizzled r->(r%T)*Bsw+r/T
//      3 = +Cadd[row*N+col]  (residual)
// Requires M%BM==0, N%BN==0, K%BK==0.
// ---------------------------------------------------------------------------
template<int BM, int BN, int BK, int TM, int TN, bool TRANSB, int EPI>
__global__ void __launch_bounds__((BM/TM)*(BN/TN))
sgemm_k(const float* __restrict__ Ag, const float* __restrict__ Bg,
        float* __restrict__ Cg,
        const float* __restrict__ bias, const float* __restrict__ bias2,
        const float* __restrict__ Cadd,
        int M, int N, int K, int Tsw, int Bsw)
{
    constexpr int NT = (BM/TM)*(BN/TN);
    constexpr int LA = (BM*BK)/(4*NT);
    constexpr int LB = (BK*BN)/(4*NT);
    static_assert(LA >= 1 && LB >= 1, "tile too small");

    __shared__ float As[2][BK][BM];
    __shared__ float Bs[2][BK][BN];

    const int tid = threadIdx.x;
    const int tr  = tid / (BN/TN);
    const int tc  = tid % (BN/TN);
    const int m0  = blockIdx.y * BM;
    const int n0  = blockIdx.x * BN;

    float acc[TM][TN];
#pragma unroll
    for (int i = 0; i < TM; i++)
#pragma unroll
        for (int j = 0; j < TN; j++) acc[i][j] = 0.f;

    auto ldg_tiles = [&](int k0, float4 (&ar)[LA], float4 (&br)[LB]) {
#pragma unroll
        for (int p = 0; p < LA; p++) {
            int i = p*NT + tid;
            int row = i / (BK/4), c4 = i % (BK/4);
            ar[p] = *reinterpret_cast<const float4*>(Ag + (size_t)(m0+row)*K + k0 + c4*4);
        }
        if (!TRANSB) {
#pragma unroll
            for (int p = 0; p < LB; p++) {
                int i = p*NT + tid;
                int row = i / (BN/4), c4 = i % (BN/4);
                br[p] = *reinterpret_cast<const float4*>(Bg + (size_t)(k0+row)*N + n0 + c4*4);
            }
        } else {
#pragma unroll
            for (int p = 0; p < LB; p++) {
                int i = p*NT + tid;
                int row = i / (BK/4), c4 = i % (BK/4);
                br[p] = *reinterpret_cast<const float4*>(Bg + (size_t)(n0+row)*K + k0 + c4*4);
            }
        }
    };

    auto sts_tiles = [&](int buf, const float4 (&ar)[LA], const float4 (&br)[LB]) {
#pragma unroll
        for (int p = 0; p < LA; p++) {
            int i = p*NT + tid;
            int row = i / (BK/4), c4 = i % (BK/4);
            As[buf][c4*4+0][row] = ar[p].x;
            As[buf][c4*4+1][row] = ar[p].y;
            As[buf][c4*4+2][row] = ar[p].z;
            As[buf][c4*4+3][row] = ar[p].w;
        }
        if (!TRANSB) {
#pragma unroll
            for (int p = 0; p < LB; p++) {
                int i = p*NT + tid;
                int row = i / (BN/4), c4 = i % (BN/4);
                *reinterpret_cast<float4*>(&Bs[buf][row][c4*4]) = br[p];
            }
        } else {
#pragma unroll
            for (int p = 0; p < LB; p++) {
                int i = p*NT + tid;
                int row = i / (BK/4), c4 = i % (BK/4);
                Bs[buf][c4*4+0][row] = br[p].x;
                Bs[buf][c4*4+1][row] = br[p].y;
                Bs[buf][c4*4+2][row] = br[p].z;
                Bs[buf][c4*4+3][row] = br[p].w;
            }
        }
    };

    {
        float4 ar[LA], br[LB];
        ldg_tiles(0, ar, br);
        sts_tiles(0, ar, br);
    }
    __syncthreads();

    const int NKT = K / BK;
    for (int kt = 0; kt < NKT; ++kt) {
        const int cur = kt & 1;
        float4 ar[LA], br[LB];
        if (kt + 1 < NKT) ldg_tiles((kt+1)*BK, ar, br);

#pragma unroll
        for (int k = 0; k < BK; k++) {
            float a[TM], b[TN];
#pragma unroll
            for (int i = 0; i < TM; i += 4) {
                float4 v = *reinterpret_cast<const float4*>(&As[cur][k][tr*TM + i]);
                a[i] = v.x; a[i+1] = v.y; a[i+2] = v.z; a[i+3] = v.w;
            }
#pragma unroll
            for (int j = 0; j < TN; j += 4) {
                float4 v = *reinterpret_cast<const float4*>(&Bs[cur][k][tc*TN + j]);
                b[j] = v.x; b[j+1] = v.y; b[j+2] = v.z; b[j+3] = v.w;
            }
#pragma unroll
            for (int i = 0; i < TM; i++)
#pragma unroll
                for (int j = 0; j < TN; j++)
                    acc[i][j] = fmaf(a[i], b[j], acc[i][j]);
        }

        if (kt + 1 < NKT) sts_tiles(cur ^ 1, ar, br);
        __syncthreads();
    }

    // Epilogue
#pragma unroll
    for (int i = 0; i < TM; i++) {
        int row = m0 + tr*TM + i;
        size_t orow = (EPI == 2) ? (size_t)((row % Tsw) * Bsw + row / Tsw) : (size_t)row;
#pragma unroll
        for (int j = 0; j < TN; j += 4) {
            int col = n0 + tc*TN + j;
            float tv[4];
#pragma unroll
            for (int q = 0; q < 4; q++) {
                float t = acc[i][j+q];
                if (EPI != 3 && bias) t += bias[col+q];
                if (EPI == 2)         t += bias2[col+q];
                if (EPI == 3)         t += Cadd[(size_t)row*N + col + q];
                if (EPI == 1)         t = t / (1.f + expf(-t));   // SiLU
                tv[q] = t;
            }
            float4 v; v.x = tv[0]; v.y = tv[1]; v.z = tv[2]; v.w = tv[3];
            *reinterpret_cast<float4*>(Cg + orow*(size_t)N + col) = v;
        }
    }
}

// ---------------------------------------------------------------------------
__device__ __forceinline__ float sigmoidf_(float x) { return 1.f / (1.f + expf(-x)); }

__global__ void lstm_cell_k(const float* __restrict__ gates,
                            const float* __restrict__ c_in,
                            float* __restrict__ c_out,
                            float* __restrict__ h_out,
                            float* __restrict__ h_seq, int t)
{
    int idx = blockIdx.x * blockDim.x + threadIdx.x;
    if (idx >= cB * cH) return;
    int b = idx / cH, j = idx % cH;
    const float* g = gates + (size_t)b * cG;
    float ig = sigmoidf_(g[j]);
    float fg = sigmoidf_(g[cH + j]);
    float gg = tanhf(g[2*cH + j]);
    float og = sigmoidf_(g[3*cH + j]);
    float c  = fg * c_in[idx] + ig * gg;
    float h  = og * tanhf(c);
    c_out[idx] = c;
    h_out[idx] = h;
    h_seq[((size_t)b * cT + t) * cH + j] = h;
}

__global__ void layernorm_k(const float* __restrict__ in, float* __restrict__ out,
                            const float* __restrict__ gw, const float* __restrict__ bw)
{
    const int row = blockIdx.x;
    const float* x = in  + (size_t)row * cH;
    float*       y = out + (size_t)row * cH;
    float s = 0.f, ss = 0.f;
    for (int i = threadIdx.x * 4; i < cH; i += blockDim.x * 4) {
        float4 v = *reinterpret_cast<const float4*>(x + i);
        s  += v.x + v.y + v.z + v.w;
        ss += v.x*v.x + v.y*v.y + v.z*v.z + v.w*v.w;
    }
    __shared__ float red[64];
    for (int o = 16; o > 0; o >>= 1) {
        s  += __shfl_xor_sync(0xffffffffu, s,  o);
        ss += __shfl_xor_sync(0xffffffffu, ss, o);
    }
    int wid = threadIdx.x / 32, lane = threadIdx.x % 32;
    if (lane == 0) { red[wid] = s; red[32 + wid] = ss; }
    __syncthreads();
    if (threadIdx.x < 32) {
        int nw = blockDim.x / 32;
        float a = (threadIdx.x < nw) ? red[threadIdx.x]      : 0.f;
        float b = (threadIdx.x < nw) ? red[32 + threadIdx.x] : 0.f;
        for (int o = 16; o > 0; o >>= 1) {
            a += __shfl_xor_sync(0xffffffffu, a, o);
            b += __shfl_xor_sync(0xffffffffu, b, o);
        }
        if (threadIdx.x == 0) { red[0] = a; red[1] = b; }
    }
    __syncthreads();
    float mu   = red[0] / cH;
    float var  = red[1] / cH - mu * mu;
    float rstd = rsqrtf(var + 1e-5f);
    for (int i = threadIdx.x * 4; i < cH; i += blockDim.x * 4) {
        float4 v  = *reinterpret_cast<const float4*>(x + i);
        float4 gv = *reinterpret_cast<const float4*>(gw + i);
        float4 bv = *reinterpret_cast<const float4*>(bw + i);
        float4 o;
        o.x = (v.x - mu) * rstd * gv.x + bv.x;
        o.y = (v.y - mu) * rstd * gv.y + bv.y;
        o.z = (v.z - mu) * rstd * gv.z + bv.z;
        o.w = (v.w - mu) * rstd * gv.w + bv.w;
        *reinterpret_cast<float4*>(y + i) = o;
    }
}

// values = x @ Wc + bc ; rew = x @ Wr + br  (one warp per row, shared x reads)
__global__ void dual_gemv_k(const float* __restrict__ x,
                            const float* __restrict__ wc, const float* __restrict__ wr,
                            const float* __restrict__ bc, const float* __restrict__ br,
                            float* __restrict__ outv, float* __restrict__ outr)
{
    int warp = (blockIdx.x * blockDim.x + threadIdx.x) / 32;
    int lane = threadIdx.x % 32;
    if (warp >= cBT) return;
    const float* xr = x + (size_t)warp * cH;
    float sc = 0.f, sr = 0.f;
    for (int i = lane * 4; i < cH; i += 128) {
        float4 xv = *reinterpret_cast<const float4*>(xr + i);
        float4 cv = *reinterpret_cast<const float4*>(wc + i);
        float4 rv = *reinterpret_cast<const float4*>(wr + i);
        sc += xv.x*cv.x + xv.y*cv.y + xv.z*cv.z + xv.w*cv.w;
        sr += xv.x*rv.x + xv.y*rv.y + xv.z*rv.z + xv.w*rv.w;
    }
    for (int o = 16; o > 0; o >>= 1) {
        sc += __shfl_xor_sync(0xffffffffu, sc, o);
        sr += __shfl_xor_sync(0xffffffffu, sr, o);
    }
    if (lane == 0) {
        outv[warp] = sc + bc[0];
        outr[warp] = sr + br[0];
    }
}

__global__ void copy2_k(const float* __restrict__ a, const float* __restrict__ b,
                        float* __restrict__ oa, float* __restrict__ ob, int n)
{
    int i = blockIdx.x * blockDim.x + threadIdx.x;
    if (i < n) { oa[i] = a[i]; ob[i] = b[i]; }
}

// ---------------------------------------------------------------------------
extern "C" void kernel_launch(void* const* d_in, const int* in_sizes, int n_in,
                              void* d_out, int out_size)
{
    const float* obs   = (const float*)d_in[0];
    const float* h0    = (const float*)d_in[1];
    const float* c0    = (const float*)d_in[2];
    const float* W1    = (const float*)d_in[3];
    const float* b1    = (const float*)d_in[4];
    const float* W2    = (const float*)d_in[5];
    const float* b2    = (const float*)d_in[6];
    const float* w_ih  = (const float*)d_in[7];
    const float* w_hh  = (const float*)d_in[8];
    const float* b_ih  = (const float*)d_in[9];
    const float* b_hh  = (const float*)d_in[10];
    const float* ln_g  = (const float*)d_in[11];
    const float* ln_b  = (const float*)d_in[12];
    const float* Wa    = (const float*)d_in[13];
    const float* ba    = (const float*)d_in[14];
    const float* Wc    = (const float*)d_in[15];
    const float* bc    = (const float*)d_in[16];
    const float* Wobs  = (const float*)d_in[17];
    const float* bobs  = (const float*)d_in[18];
    const float* Wr    = (const float*)d_in[19];
    const float* br    = (const float*)d_in[20];
    float* out = (float*)d_out;

    float *enc1, *enc2, *gx, *hseq, *gates, *hb, *cb;
    cudaGetSymbolAddress((void**)&enc1,  g_enc1);
    cudaGetSymbolAddress((void**)&enc2,  g_enc2);
    cudaGetSymbolAddress((void**)&gx,    g_gx);
    cudaGetSymbolAddress((void**)&hseq,  g_hseq);
    cudaGetSymbolAddress((void**)&gates, g_gates);
    cudaGetSymbolAddress((void**)&hb,    g_hbuf);
    cudaGetSymbolAddress((void**)&cb,    g_cbuf);
    float* hbuf[2] = { hb, hb + (size_t)cB * cH };
    float* cbuf[2] = { cb, cb + (size_t)cB * cH };

    // 1) enc1 = silu(obs @ W1 + b1)   [32768,512]x[512,1024]
    {
        dim3 grid(cE/128, cBT/128);
        sgemm_k<128,128,16,8,8,false,1><<<grid, 256>>>(
            obs, W1, enc1, b1, nullptr, nullptr, cBT, cE, cOBS, 0, 0);
    }
    // 2) enc2 = silu(enc1 @ W2 + b2)  [32768,1024]x[1024,1024]
    {
        dim3 grid(cE/128, cBT/128);
        sgemm_k<128,128,16,8,8,false,1><<<grid, 256>>>(
            enc1, W2, enc2, b2, nullptr, nullptr, cBT, cE, cE, 0, 0);
    }
    // 3) gx = enc2 @ w_ih^T + (b_ih + b_hh), stored [T,B,4H]
    {
        dim3 grid(cG/128, cBT/128);
        sgemm_k<128,128,16,8,8,true,2><<<grid, 256>>>(
            enc2, w_ih, gx, b_ih, b_hh, nullptr, cBT, cG, cE, cT, cB);
    }
    // 4) LSTM scan
    {
        const float* hin = h0;
        const float* cin = c0;
        dim3 ggrid(cG/128, cB/64);
        int cellBlocks = (cB * cH + 255) / 256;
        for (int t = 0; t < cT; ++t) {
            sgemm_k<64,128,16,4,8,true,3><<<ggrid, 256>>>(
                hin, w_hh, gates, nullptr, nullptr,
                gx + (size_t)t * cB * cG, cB, cG, cH, 0, 0);
            float* hout = hbuf[t & 1];
            float* cout = cbuf[t & 1];
            lstm_cell_k<<<cellBlocks, 256>>>(gates, cin, cout, hout, hseq, t);
            hin = hout;
            cin = cout;
        }
        // final h/c -> d_out
        copy2_k<<<(cB*cH + 255)/256, 256>>>(hin, cin, out + OFF_HT, out + OFF_CT, cB*cH);
    }
    // 5) x = layernorm(hseq)  (reuse enc1 as x)
    layernorm_k<<<cBT, 256>>>(hseq, enc1, ln_g, ln_b);
    // 6) logits = x @ Wa + ba   [32768,1024]x[1024,64]
    {
        dim3 grid(cA/64, cBT/128);
        sgemm_k<128,64,16,8,4,false,0><<<grid, 256>>>(
            enc1, Wa, out + OFF_LOGITS, ba, nullptr, nullptr, cBT, cA, cH, 0, 0);
    }
    // 7) obs_pred = x @ Wobs + bobs  [32768,1024]x[1024,512]
    {
        dim3 grid(cOBS/128, cBT/128);
        sgemm_k<128,128,16,8,8,false,0><<<grid, 256>>>(
            enc1, Wobs, out + OFF_OBS, bobs, nullptr, nullptr, cBT, cOBS, cH, 0, 0);
    }
    // 8) values / rew_pred (dual GEMV)
    dual_gemv_k<<<(cBT*32 + 255)/256, 256>>>(
        enc1, Wc, Wr, bc, br, out + OFF_VAL, out + OFF_REW);
}

// round 4
// speedup vs baseline: 2.1169x; 2.1169x over previous
#include <cuda_runtime.h>
#include <cuda_bf16.h>
#include <cstdint>
#include <cstddef>

constexpr int cB=256, cT=128, cOBS=512, cE=1024, cH=1024, cA=64;
constexpr int cBT=cB*cT, cG=4*cH;

constexpr size_t OFF_LOGITS=0;
constexpr size_t OFF_VAL = OFF_LOGITS + (size_t)cBT*cA;
constexpr size_t OFF_OBS = OFF_VAL + (size_t)cBT;
constexpr size_t OFF_REW = OFF_OBS + (size_t)cBT*cOBS;
constexpr size_t OFF_HT  = OFF_REW + (size_t)cBT;
constexpr size_t OFF_CT  = OFF_HT + (size_t)cB*cH;

typedef __nv_bfloat16 bf16;
// activations (split)
__device__ bf16 g_obs_h[(size_t)cBT*cOBS], g_obs_l[(size_t)cBT*cOBS];
__device__ bf16 g_e1h[(size_t)cBT*cE], g_e1l[(size_t)cBT*cE];
__device__ bf16 g_e2h[(size_t)cBT*cE], g_e2l[(size_t)cBT*cE];
__device__ bf16 g_xh[(size_t)cBT*cH], g_xl[(size_t)cBT*cH];
__device__ bf16 g_hh[(size_t)cB*cH], g_hl[(size_t)cB*cH];
__device__ float g_gx[(size_t)cBT*cG];     // [T,B,4H]
__device__ float g_hseq[(size_t)cBT*cH];   // [B,T,H]
__device__ float g_gates[(size_t)cB*cG];
__device__ float g_c[(size_t)cB*cH];
// weights (split, [N,K])
__device__ bf16 g_w1h[(size_t)cE*cOBS], g_w1l[(size_t)cE*cOBS];
__device__ bf16 g_w2h[(size_t)cE*cE],   g_w2l[(size_t)cE*cE];
__device__ bf16 g_wah[(size_t)cA*cH],   g_wal[(size_t)cA*cH];
__device__ bf16 g_woh[(size_t)cOBS*cH], g_wol[(size_t)cOBS*cH];
__device__ bf16 g_wihh[(size_t)cG*cE],  g_wihl[(size_t)cG*cE];
__device__ bf16 g_whhh[(size_t)cG*cH],  g_whhl[(size_t)cG*cH];

__device__ __forceinline__ uint32_t smem_u32(const void* p){
    uint32_t a; asm("{ .reg .u64 t; cvta.to.shared.u64 t, %1; cvt.u32.u64 %0, t; }":"=r"(a):"l"(p)); return a;
}
__device__ __forceinline__ void split2(float v, bf16& h, bf16& l){
    h = __float2bfloat16(v); l = __float2bfloat16(v - __bfloat162float(h));
}
__device__ __forceinline__ void cpasync16(uint32_t d, const void* g){
    asm volatile("cp.async.cg.shared.global [%0], [%1], 16;"::"r"(d),"l"(g):"memory");
}
__device__ __forceinline__ void ldsm4(uint32_t (&r)[4], uint32_t a){
    asm volatile("ldmatrix.sync.aligned.m8n8.x4.shared.b16 {%0,%1,%2,%3}, [%4];"
        : "=r"(r[0]),"=r"(r[1]),"=r"(r[2]),"=r"(r[3]) : "r"(a));
}
__device__ __forceinline__ void mma16816(float (&d)[4], const uint32_t (&a)[4],
                                         uint32_t b0, uint32_t b1){
    asm volatile("mma.sync.aligned.m16n8k16.row.col.f32.bf16.bf16.f32 "
        "{%0,%1,%2,%3}, {%4,%5,%6,%7}, {%8,%9}, {%0,%1,%2,%3};"
        : "+f"(d[0]),"+f"(d[1]),"+f"(d[2]),"+f"(d[3])
        : "r"(a[0]),"r"(a[1]),"r"(a[2]),"r"(a[3]),"r"(b0),"r"(b1));
}

// ---------------------------------------------------------------------------
// Tensor GEMM (mma.sync bf16): D[128 x BN] per CTA = sum_seg A_seg[M,K]*B_seg[N,K]^T
// segs: (Ah,Bh),(Ah,Bl),(Al,Bh).
// EPI: 0=+bias->f32 ; 1=silu(+bias)->split bf16 ; 2=+bias+bias2 with row swizzle
// r->(r%Tsw)*Bsw+r/Tsw ->f32 ; 3=+Cadd->f32
// ---------------------------------------------------------------------------
template<int BN, int EPI>
__global__ void __launch_bounds__(256)
tgemm_k(const bf16* __restrict__ Ah, const bf16* __restrict__ Al,
        const bf16* __restrict__ Bh, const bf16* __restrict__ Bl,
        float* __restrict__ Cf, bf16* __restrict__ Ch, bf16* __restrict__ Cl,
        const float* __restrict__ bias, const float* __restrict__ bias2,
        const float* __restrict__ Cadd, int Ngl, int K, int Tsw, int Bsw)
{
    constexpr int BM=128, BK=32, STR=40;           // padded smem row (bf16 elems)
    constexpr int ABYTES = BM*STR*2, BBYTES = BN*STR*2;
    constexpr int BNW = BN/2;                      // per n-warp width
    constexpr int NP  = BNW/16;                    // ldmatrix.x4 count for B
    constexpr int NT8 = BNW/8;                     // n8 tiles per warp
    constexpr int APT = (BM*BK)/(8*256);           // 2
    constexpr int BPT = (BN*BK)/(8*256);           // 2 or 1

    __shared__ bf16 sm[(2*ABYTES + 2*BBYTES)/2];
    const uint32_t sA = smem_u32(sm);
    const uint32_t sB = sA + 2*ABYTES;

    const int tid = threadIdx.x, lane = tid & 31, wid = tid >> 5;
    const int wm = wid & 3, wn = wid >> 2;
    const int m0 = blockIdx.y * BM, n0 = blockIdx.x * BN;

    float acc[2][NT8][4];
#pragma unroll
    for (int i = 0; i < 2; i++)
#pragma unroll
        for (int j = 0; j < NT8; j++)
#pragma unroll
            for (int q = 0; q < 4; q++) acc[i][j][q] = 0.f;

    const int cpseg = K / BK, NT = 3 * cpseg;

    auto load_tile = [&](int c, int buf){
        const int seg = c / cpseg, kk = (c - seg*cpseg) * BK;
        const bf16* Ap = (seg == 2) ? Al : Ah;
        const bf16* Bp = (seg == 1) ? Bl : Bh;
#pragma unroll
        for (int p = 0; p < APT; p++) {
            int i = p*256 + tid, r = i >> 2, c8 = i & 3;
            cpasync16(sA + buf*ABYTES + (r*STR + c8*8)*2,
                      Ap + (size_t)(m0 + r)*K + kk + c8*8);
        }
#pragma unroll
        for (int p = 0; p < BPT; p++) {
            int i = p*256 + tid, r = i >> 2, c8 = i & 3;
            cpasync16(sB + buf*BBYTES + (r*STR + c8*8)*2,
                      Bp + (size_t)(n0 + r)*K + kk + c8*8);
        }
        asm volatile("cp.async.commit_group;" ::: "memory");
    };

    // ldmatrix per-lane offsets (element units)
    const int aRow = wm*32 + (lane & 15);
    const int aCol = (lane >> 4) * 8;
    const int bRow = wn*BNW + (lane & 7) + ((lane >> 4) & 1) * 8;
    const int bCol = ((lane >> 3) & 1) * 8;

    load_tile(0, 0);
    for (int c = 0; c < NT; ++c) {
        const int buf = c & 1;
        if (c + 1 < NT) {
            load_tile(c + 1, buf ^ 1);
            asm volatile("cp.async.wait_group 1;" ::: "memory");
        } else {
            asm volatile("cp.async.wait_group 0;" ::: "memory");
        }
        __syncthreads();

#pragma unroll
        for (int kk2 = 0; kk2 < BK; kk2 += 16) {
            uint32_t a[2][4];
#pragma unroll
            for (int mi = 0; mi < 2; mi++)
                ldsm4(a[mi], sA + buf*ABYTES + ((aRow + mi*16)*STR + kk2 + aCol)*2);
            uint32_t b[NP][4];
#pragma unroll
            for (int np = 0; np < NP; np++)
                ldsm4(b[np], sB + buf*BBYTES + ((bRow + np*16)*STR + kk2 + bCol)*2);
#pragma unroll
            for (int mi = 0; mi < 2; mi++)
#pragma unroll
                for (int np = 0; np < NP; np++) {
                    mma16816(acc[mi][2*np],   a[mi], b[np][0], b[np][1]);
                    mma16816(acc[mi][2*np+1], a[mi], b[np][2], b[np][3]);
                }
        }
        __syncthreads();   // protect buf reuse by next cp.async
    }

    // epilogue
    const int g = lane >> 2, t = lane & 3;
    auto emit = [&](int row, int col, float v0, float v1){
        if constexpr (EPI == 1) {
            v0 += bias[col]; v1 += bias[col+1];
            v0 = v0 / (1.f + expf(-v0)); v1 = v1 / (1.f + expf(-v1));
            bf16 h0,l0,h1,l1; split2(v0,h0,l0); split2(v1,h1,l1);
            *reinterpret_cast<__nv_bfloat162*>(Ch + (size_t)row*Ngl + col) = __halves2bfloat162(h0,h1);
            *reinterpret_cast<__nv_bfloat162*>(Cl + (size_t)row*Ngl + col) = __halves2bfloat162(l0,l1);
        } else if constexpr (EPI == 0) {
            float2 o; o.x = v0 + bias[col]; o.y = v1 + bias[col+1];
            *reinterpret_cast<float2*>(Cf + (size_t)row*Ngl + col) = o;
        } else if constexpr (EPI == 2) {
            size_t orow = (size_t)((row % Tsw) * Bsw + row / Tsw);
            float2 o; o.x = v0 + bias[col] + bias2[col]; o.y = v1 + bias[col+1] + bias2[col+1];
            *reinterpret_cast<float2*>(Cf + orow*(size_t)Ngl + col) = o;
        } else {
            float2 a2 = *reinterpret_cast<const float2*>(Cadd + (size_t)row*Ngl + col);
            float2 o; o.x = v0 + a2.x; o.y = v1 + a2.y;
            *reinterpret_cast<float2*>(Cf + (size_t)row*Ngl + col) = o;
        }
    };
#pragma unroll
    for (int mi = 0; mi < 2; mi++)
#pragma unroll
        for (int ni = 0; ni < NT8; ni++) {
            int row = m0 + wm*32 + mi*16 + g;
            int col = n0 + wn*BNW + ni*8 + 2*t;
            emit(row,     col, acc[mi][ni][0], acc[mi][ni][1]);
            emit(row + 8, col, acc[mi][ni][2], acc[mi][ni][3]);
        }
}

// ---------------- conversion / pointwise kernels ----------------
__global__ void conv_split_k(const float* __restrict__ in, bf16* __restrict__ oh,
                             bf16* __restrict__ ol, size_t n4)
{
    size_t i = (size_t)blockIdx.x*blockDim.x + threadIdx.x;
    if (i >= n4) return;
    float4 v = reinterpret_cast<const float4*>(in)[i];
    bf16 h0,l0,h1,l1,h2,l2,h3,l3;
    split2(v.x,h0,l0); split2(v.y,h1,l1); split2(v.z,h2,l2); split2(v.w,h3,l3);
    reinterpret_cast<__nv_bfloat162*>(oh)[i*2]   = __halves2bfloat162(h0,h1);
    reinterpret_cast<__nv_bfloat162*>(oh)[i*2+1] = __halves2bfloat162(h2,h3);
    reinterpret_cast<__nv_bfloat162*>(ol)[i*2]   = __halves2bfloat162(l0,l1);
    reinterpret_cast<__nv_bfloat162*>(ol)[i*2+1] = __halves2bfloat162(l2,l3);
}
__global__ void convT_k(const float* __restrict__ W, bf16* __restrict__ oh,
                        bf16* __restrict__ ol, int K, int N)
{
    __shared__ float t[32][33];
    int tx = threadIdx.x, ty = threadIdx.y;
#pragma unroll
    for (int r = 0; r < 4; r++)
        t[ty+8*r][tx] = W[(size_t)(blockIdx.y*32 + ty + 8*r)*N + blockIdx.x*32 + tx];
    __syncthreads();
#pragma unroll
    for (int r = 0; r < 4; r++) {
        int n = blockIdx.x*32 + ty + 8*r, k = blockIdx.y*32 + tx;
        bf16 h, l; split2(t[tx][ty+8*r], h, l);
        oh[(size_t)n*K + k] = h; ol[(size_t)n*K + k] = l;
    }
}
__global__ void copy1_k(const float* __restrict__ a, float* __restrict__ o, int n){
    int i = blockIdx.x*blockDim.x + threadIdx.x; if (i < n) o[i] = a[i];
}
__device__ __forceinline__ float sigm_(float x){ return 1.f/(1.f+expf(-x)); }

__global__ void lstm_cell_k(const float* __restrict__ gates, const float* __restrict__ c_in,
                            float* __restrict__ c_out, bf16* __restrict__ hh, bf16* __restrict__ hl,
                            float* __restrict__ hseq, int t)
{
    int idx = blockIdx.x*blockDim.x + threadIdx.x;
    if (idx >= cB*cH) return;
    int b = idx / cH, j = idx % cH;
    const float* g = gates + (size_t)b*cG;
    float ig = sigm_(g[j]), fg = sigm_(g[cH+j]);
    float gg = tanhf(g[2*cH+j]), og = sigm_(g[3*cH+j]);
    float c = fg * c_in[idx] + ig * gg;
    float h = og * tanhf(c);
    c_out[idx] = c;
    bf16 h_, l_; split2(h, h_, l_);
    hh[idx] = h_; hl[idx] = l_;
    hseq[((size_t)b*cT + t)*cH + j] = h;
}
__global__ void hc_out_k(const float* __restrict__ hseq, const float* __restrict__ c,
                         float* __restrict__ oh, float* __restrict__ oc)
{
    int idx = blockIdx.x*blockDim.x + threadIdx.x;
    if (idx >= cB*cH) return;
    int b = idx / cH, j = idx % cH;
    oh[idx] = hseq[((size_t)b*cT + cT-1)*cH + j];
    oc[idx] = c[idx];
}
__global__ void layernorm_k(const float* __restrict__ in, bf16* __restrict__ oh,
                            bf16* __restrict__ ol, const float* __restrict__ gw,
                            const float* __restrict__ bw)
{
    const int row = blockIdx.x;
    const float* x = in + (size_t)row*cH;
    float s = 0.f, ss = 0.f;
    for (int i = threadIdx.x*4; i < cH; i += blockDim.x*4) {
        float4 v = *reinterpret_cast<const float4*>(x + i);
        s += v.x+v.y+v.z+v.w; ss += v.x*v.x+v.y*v.y+v.z*v.z+v.w*v.w;
    }
    __shared__ float red[64];
    for (int o = 16; o > 0; o >>= 1) { s += __shfl_xor_sync(~0u,s,o); ss += __shfl_xor_sync(~0u,ss,o); }
    int w = threadIdx.x/32, lane = threadIdx.x%32;
    if (lane == 0) { red[w] = s; red[32+w] = ss; }
    __syncthreads();
    if (threadIdx.x < 32) {
        int nw = blockDim.x/32;
        float a = (threadIdx.x < nw) ? red[threadIdx.x] : 0.f;
        float b = (threadIdx.x < nw) ? red[32+threadIdx.x] : 0.f;
        for (int o = 16; o > 0; o >>= 1) { a += __shfl_xor_sync(~0u,a,o); b += __shfl_xor_sync(~0u,b,o); }
        if (threadIdx.x == 0) { red[0] = a; red[1] = b; }
    }
    __syncthreads();
    float mu = red[0]/cH, var = red[1]/cH - mu*mu, rstd = rsqrtf(var + 1e-5f);
    for (int i = threadIdx.x*4; i < cH; i += blockDim.x*4) {
        float4 v = *reinterpret_cast<const float4*>(x + i);
        float4 gv = *reinterpret_cast<const float4*>(gw + i);
        float4 bv = *reinterpret_cast<const float4*>(bw + i);
        float y0 = (v.x-mu)*rstd*gv.x + bv.x, y1 = (v.y-mu)*rstd*gv.y + bv.y;
        float y2 = (v.z-mu)*rstd*gv.z + bv.z, y3 = (v.w-mu)*rstd*gv.w + bv.w;
        bf16 h0,l0,h1,l1,h2,l2,h3,l3;
        split2(y0,h0,l0); split2(y1,h1,l1); split2(y2,h2,l2); split2(y3,h3,l3);
        __nv_bfloat162* ph = reinterpret_cast<__nv_bfloat162*>(oh + (size_t)row*cH + i);
        __nv_bfloat162* pl = reinterpret_cast<__nv_bfloat162*>(ol + (size_t)row*cH + i);
        ph[0] = __halves2bfloat162(h0,h1); ph[1] = __halves2bfloat162(h2,h3);
        pl[0] = __halves2bfloat162(l0,l1); pl[1] = __halves2bfloat162(l2,l3);
    }
}
__global__ void dual_gemv_k(const bf16* __restrict__ xh, const bf16* __restrict__ xl,
                            const float* __restrict__ wc, const float* __restrict__ wr,
                            const float* __restrict__ bc, const float* __restrict__ br,
                            float* __restrict__ outv, float* __restrict__ outr)
{
    int warp = (blockIdx.x*blockDim.x + threadIdx.x) >> 5;
    int lane = threadIdx.x & 31;
    if (warp >= cBT) return;
    const bf16* xhr = xh + (size_t)warp*cH;
    const bf16* xlr = xl + (size_t)warp*cH;
    float sc = 0.f, sr = 0.f;
    for (int i = lane*8; i < cH; i += 256) {
        uint4 uh = *reinterpret_cast<const uint4*>(xhr + i);
        uint4 ul = *reinterpret_cast<const uint4*>(xlr + i);
        const uint32_t* ph = &uh.x; const uint32_t* pl = &ul.x;
#pragma unroll
        for (int q = 0; q < 4; q++) {
            float2 fh = __bfloat1622float2(*reinterpret_cast<const __nv_bfloat162*>(&ph[q]));
            float2 fl = __bfloat1622float2(*reinterpret_cast<const __nv_bfloat162*>(&pl[q]));
            float x0 = fh.x + fl.x, x1 = fh.y + fl.y;
            sc += x0*wc[i+q*2] + x1*wc[i+q*2+1];
            sr += x0*wr[i+q*2] + x1*wr[i+q*2+1];
        }
    }
    for (int o = 16; o > 0; o >>= 1) { sc += __shfl_xor_sync(~0u,sc,o); sr += __shfl_xor_sync(~0u,sr,o); }
    if (lane == 0) { outv[warp] = sc + bc[0]; outr[warp] = sr + br[0]; }
}

// ---------------------------------------------------------------------------
extern "C" void kernel_launch(void* const* d_in, const int* in_sizes, int n_in,
                              void* d_out, int out_size)
{
    const float* obs  = (const float*)d_in[0];
    const float* h0   = (const float*)d_in[1];
    const float* c0   = (const float*)d_in[2];
    const float* W1   = (const float*)d_in[3];
    const float* b1   = (const float*)d_in[4];
    const float* W2   = (const float*)d_in[5];
    const float* b2   = (const float*)d_in[6];
    const float* w_ih = (const float*)d_in[7];
    const float* w_hh = (const float*)d_in[8];
    const float* b_ih = (const float*)d_in[9];
    const float* b_hh = (const float*)d_in[10];
    const float* ln_g = (const float*)d_in[11];
    const float* ln_b = (const float*)d_in[12];
    const float* Wa   = (const float*)d_in[13];
    const float* ba   = (const float*)d_in[14];
    const float* Wc   = (const float*)d_in[15];
    const float* bc   = (const float*)d_in[16];
    const float* Wobs = (const float*)d_in[17];
    const float* bobs = (const float*)d_in[18];
    const float* Wr   = (const float*)d_in[19];
    const float* br   = (const float*)d_in[20];
    float* out = (float*)d_out;

    bf16 *obs_h,*obs_l,*e1h,*e1l,*e2h,*e2l,*xh,*xl,*hh,*hl;
    bf16 *w1h,*w1l,*w2h,*w2l,*wah,*wal,*woh,*wol,*wihh,*wihl,*whhh,*whhl;
    float *gx,*hseq,*gates,*cbuf;
    cudaGetSymbolAddress((void**)&obs_h, g_obs_h); cudaGetSymbolAddress((void**)&obs_l, g_obs_l);
    cudaGetSymbolAddress((void**)&e1h, g_e1h); cudaGetSymbolAddress((void**)&e1l, g_e1l);
    cudaGetSymbolAddress((void**)&e2h, g_e2h); cudaGetSymbolAddress((void**)&e2l, g_e2l);
    cudaGetSymbolAddress((void**)&xh, g_xh);   cudaGetSymbolAddress((void**)&xl, g_xl);
    cudaGetSymbolAddress((void**)&hh, g_hh);   cudaGetSymbolAddress((void**)&hl, g_hl);
    cudaGetSymbolAddress((void**)&w1h, g_w1h); cudaGetSymbolAddress((void**)&w1l, g_w1l);
    cudaGetSymbolAddress((void**)&w2h, g_w2h); cudaGetSymbolAddress((void**)&w2l, g_w2l);
    cudaGetSymbolAddress((void**)&wah, g_wah); cudaGetSymbolAddress((void**)&wal, g_wal);
    cudaGetSymbolAddress((void**)&woh, g_woh); cudaGetSymbolAddress((void**)&wol, g_wol);
    cudaGetSymbolAddress((void**)&wihh, g_wihh); cudaGetSymbolAddress((void**)&wihl, g_wihl);
    cudaGetSymbolAddress((void**)&whhh, g_whhh); cudaGetSymbolAddress((void**)&whhl, g_whhl);
    cudaGetSymbolAddress((void**)&gx, g_gx);   cudaGetSymbolAddress((void**)&hseq, g_hseq);
    cudaGetSymbolAddress((void**)&gates, g_gates); cudaGetSymbolAddress((void**)&cbuf, g_c);

    // conversions
    conv_split_k<<<((size_t)cBT*cOBS/4 + 255)/256, 256>>>(obs, obs_h, obs_l, (size_t)cBT*cOBS/4);
    conv_split_k<<<((size_t)cB*cH/4 + 255)/256, 256>>>(h0, hh, hl, (size_t)cB*cH/4);
    copy1_k<<<(cB*cH + 255)/256, 256>>>(c0, cbuf, cB*cH);
    conv_split_k<<<((size_t)cG*cE/4 + 255)/256, 256>>>(w_ih, wihh, wihl, (size_t)cG*cE/4);
    conv_split_k<<<((size_t)cG*cH/4 + 255)/256, 256>>>(w_hh, whhh, whhl, (size_t)cG*cH/4);
    { dim3 b(32,8); convT_k<<<dim3(cE/32, cOBS/32), b>>>(W1, w1h, w1l, cOBS, cE);
      convT_k<<<dim3(cE/32, cE/32), b>>>(W2, w2h, w2l, cE, cE);
      convT_k<<<dim3(cA/32, cH/32), b>>>(Wa, wah, wal, cH, cA);
      convT_k<<<dim3(cOBS/32, cH/32), b>>>(Wobs, woh, wol, cH, cOBS); }

    // 1) enc1 = silu(obs @ W1 + b1)
    tgemm_k<128,1><<<dim3(cE/128, cBT/128), 256>>>(
        obs_h, obs_l, w1h, w1l, nullptr, e1h, e1l, b1, nullptr, nullptr, cE, cOBS, 0, 0);
    // 2) enc2 = silu(enc1 @ W2 + b2)
    tgemm_k<128,1><<<dim3(cE/128, cBT/128), 256>>>(
        e1h, e1l, w2h, w2l, nullptr, e2h, e2l, b2, nullptr, nullptr, cE, cE, 0, 0);
    // 3) gx = enc2 @ w_ih^T + (b_ih + b_hh), stored [T,B,4H]
    tgemm_k<128,2><<<dim3(cG/128, cBT/128), 256>>>(
        e2h, e2l, wihh, wihl, gx, nullptr, nullptr, b_ih, b_hh, nullptr, cG, cE, cT, cB);
    // 4) scan
    for (int t = 0; t < cT; ++t) {
        tgemm_k<64,3><<<dim3(cG/64, cB/128), 256>>>(
            hh, hl, whhh, whhl, gates, nullptr, nullptr, nullptr, nullptr,
            gx + (size_t)t*cB*cG, cG, cH, 0, 0);
        lstm_cell_k<<<(cB*cH + 255)/256, 256>>>(
            gates, (t == 0) ? c0 : cbuf, cbuf, hh, hl, hseq, t);
    }
    hc_out_k<<<(cB*cH + 255)/256, 256>>>(hseq, cbuf, out + OFF_HT, out + OFF_CT);
    // 5) layernorm -> split bf16 x
    layernorm_k<<<cBT, 256>>>(hseq, xh, xl, ln_g, ln_b);
    // 6) logits
    tgemm_k<64,0><<<dim3(cA/64, cBT/128), 256>>>(
        xh, xl, wah, wal, out + OFF_LOGITS, nullptr, nullptr, ba, nullptr, nullptr, cA, cH, 0, 0);
    // 7) obs_pred
    tgemm_k<128,0><<<dim3(cOBS/128, cBT/128), 256>>>(
        xh, xl, woh, wol, out + OFF_OBS, nullptr, nullptr, bobs, nullptr, nullptr, cOBS, cH, 0, 0);
    // 8) values / rew
    dual_gemv_k<<<(cBT*32 + 255)/256, 256>>>(xh, xl, Wc, Wr, bc, br, out + OFF_VAL, out + OFF_REW);
}